// round 12
// baseline (speedup 1.0000x reference)
#include <cuda_runtime.h>
#include <cstdint>
#include <cstddef>

// PHMLinear via mma.sync tf32. Per CTA tile = 16 rows, 256 threads / 8 warps,
// each warp owns one 16-vrow m-tile.
//  MMA1: y1[(row,a), er] = sum_i x[row,a*128+i]*Wrl[e,i,r]   M=128,N=32,K=128
//  PhB : u[(row,c), er]  = sum_a y1[(row,a),er]*Wl[e,a,c]    CUDA cores, u in regs
//  MMA2: out[(row,c), o] = sum_er u[(row,c),er]*Wrr[e,r,o]   M=128,N=128,K=32

__device__ float g_wrrT[128 * 32];   // [o][er], tf32-rounded

__device__ __forceinline__ uint32_t to_tf32(float f) {
    uint32_t r;
    asm("cvt.rna.tf32.f32 %0, %1;" : "=r"(r) : "f"(f));
    return r;
}

__global__ void phm_prep(const float* __restrict__ wrr) {
    int idx = blockIdx.x * blockDim.x + threadIdx.x;
    if (idx < 4096) {
        int o = idx >> 5, er = idx & 31;
        g_wrrT[idx] = __uint_as_float(to_tf32(wrr[er * 128 + o]));
    }
}

__device__ __forceinline__ void mma8(float& d0, float& d1, float& d2, float& d3,
                                     uint32_t a0, uint32_t a1, uint32_t a2, uint32_t a3,
                                     uint32_t b0, uint32_t b1) {
    asm volatile(
        "mma.sync.aligned.m16n8k8.row.col.f32.tf32.tf32.f32 "
        "{%0,%1,%2,%3}, {%4,%5,%6,%7}, {%8,%9}, {%0,%1,%2,%3};"
        : "+f"(d0), "+f"(d1), "+f"(d2), "+f"(d3)
        : "r"(a0), "r"(a1), "r"(a2), "r"(a3), "r"(b0), "r"(b1));
}

__global__ void __launch_bounds__(256, 3)
phm_tc(const float* __restrict__ x,
       const float* __restrict__ wrl,   // [8][128][4]
       const float* __restrict__ wlf,   // [8][8][8]
       float* __restrict__ out,
       int nrows)
{
    // Region A: x chunk [128 vrow][32 pad36] -> y1T [32 er][128 vrow pad132] -> D_s [128 t][32 pad36]
    __shared__ __align__(16) float sA[4608];
    // Region B: WrlT [32 er][128 i pad132] -> WrrT [128 o][32 er pad36]
    __shared__ __align__(16) float sB[4608];
    __shared__ __align__(16) float s_wl[512];   // [e][c][a]

    const int tid  = threadIdx.x;
    const int lane = tid & 31;
    const int wid  = tid >> 5;   // 0..7, owns m-tile wid (vrows wid*16..wid*16+15)
    const int g  = lane >> 2;    // mma groupID
    const int tg = lane & 3;     // mma threadID-in-group
    int row0 = blockIdx.x * 16;
    if (row0 >= nrows) return;

    // ---- stage WrlT (tf32) + wl ----
    #pragma unroll
    for (int k = 0; k < 16; k++) {
        int m = tid + 256 * k;                 // [e][i][r] row-major, 4096
        int e = m >> 9, i = (m & 511) >> 2, r = m & 3;
        sB[(e * 4 + r) * 132 + i] = __uint_as_float(to_tf32(wrl[m]));
    }
    #pragma unroll
    for (int k = 0; k < 2; k++) {
        int m = tid + 256 * k;                 // [e][a][c], 512
        int e = m >> 6, a = (m >> 3) & 7, c = m & 7;
        s_wl[e * 64 + c * 8 + a] = wlf[m];
    }
    __syncthreads();

    const int mbase = wid * 16;

    // ---- MMA1: y accum [nt][4], single m-tile per warp ----
    float y[4][4];
    #pragma unroll
    for (int nt = 0; nt < 4; nt++)
        #pragma unroll
        for (int j = 0; j < 4; j++) y[nt][j] = 0.0f;

    #pragma unroll 1
    for (int kc = 0; kc < 4; kc++) {
        // stage x chunk [vrow][i' 32] pad 36, tf32
        #pragma unroll
        for (int k = 0; k < 4; k++) {
            int f4 = tid + 256 * k;            // 1024 float4
            int vrow = f4 >> 3, i4 = f4 & 7;
            int row = row0 + (vrow >> 3);
            if (row >= nrows) row = nrows - 1;
            float4 v = *(const float4*)(x + (size_t)row * 1024 + (vrow & 7) * 128 + kc * 32 + i4 * 4);
            v.x = __uint_as_float(to_tf32(v.x));
            v.y = __uint_as_float(to_tf32(v.y));
            v.z = __uint_as_float(to_tf32(v.z));
            v.w = __uint_as_float(to_tf32(v.w));
            *(float4*)(sA + vrow * 36 + i4 * 4) = v;
        }
        __syncthreads();
        #pragma unroll
        for (int kt = 0; kt < 4; kt++) {
            const float* xa = sA + mbase * 36 + kt * 8 + tg;
            uint32_t a0 = __float_as_uint(xa[g * 36]);
            uint32_t a1 = __float_as_uint(xa[(g + 8) * 36]);
            uint32_t a2 = __float_as_uint(xa[g * 36 + 4]);
            uint32_t a3 = __float_as_uint(xa[(g + 8) * 36 + 4]);
            #pragma unroll
            for (int nt = 0; nt < 4; nt++) {
                const float* bb = sB + (nt * 8 + g) * 132 + kc * 32 + kt * 8 + tg;
                uint32_t b0 = __float_as_uint(bb[0]);
                uint32_t b1 = __float_as_uint(bb[4]);
                mma8(y[nt][0], y[nt][1], y[nt][2], y[nt][3], a0, a1, a2, a3, b0, b1);
            }
        }
        __syncthreads();
    }

    // ---- write y1T [er][vrow pad132] into region A (x dead) ----
    #pragma unroll
    for (int nt = 0; nt < 4; nt++) {
        int vr = mbase + g;
        int er = nt * 8 + tg * 2;
        sA[er * 132 + vr]           = y[nt][0];
        sA[(er + 1) * 132 + vr]     = y[nt][1];
        sA[er * 132 + vr + 8]       = y[nt][2];
        sA[(er + 1) * 132 + vr + 8] = y[nt][3];
    }

    // ---- stage WrrT [o][er pad36] into region B (WrlT dead) ----
    #pragma unroll
    for (int k = 0; k < 4; k++) {
        int f4 = tid + 256 * k;                // 1024 float4
        int o = f4 >> 3, e4 = f4 & 7;
        *(float4*)(sB + o * 36 + e4 * 4) = *(const float4*)(g_wrrT + o * 32 + e4 * 4);
    }
    __syncthreads();

    // ---- Phase B: uu[rp][e] for this lane's (g=c, tg); er = 4e+tg;
    //      t = wid*16 + rp*8 + g, row = t>>3 = wid*2+rp, c = g ----
    uint32_t uu[2][8];
    #pragma unroll
    for (int e = 0; e < 8; e++) {
        int er = 4 * e + tg;
        float4 w0 = *(const float4*)(s_wl + e * 64 + g * 8);
        float4 w1 = *(const float4*)(s_wl + e * 64 + g * 8 + 4);
        #pragma unroll
        for (int rp = 0; rp < 2; rp++) {
            int vb = (wid * 2 + rp) * 8;
            float4 y0 = *(const float4*)(sA + er * 132 + vb);
            float4 y1v = *(const float4*)(sA + er * 132 + vb + 4);
            float u = y0.x * w0.x + y0.y * w0.y + y0.z * w0.z + y0.w * w0.w
                    + y1v.x * w1.x + y1v.y * w1.y + y1v.z * w1.z + y1v.w * w1.w;
            uu[rp][e] = to_tf32(u);
        }
    }
    __syncthreads();   // y1T reads done before D_s overlays region A

    // ---- MMA2 in 4 N-quarters + epilogue ----
    #pragma unroll 1
    for (int qn = 0; qn < 4; qn++) {
        float d[4][4];
        #pragma unroll
        for (int nl = 0; nl < 4; nl++)
            #pragma unroll
            for (int j = 0; j < 4; j++) d[nl][j] = 0.0f;

        #pragma unroll
        for (int kt = 0; kt < 4; kt++)
            #pragma unroll
            for (int nl = 0; nl < 4; nl++) {
                int o = qn * 32 + nl * 8 + g;
                const float* bb = sB + o * 36 + kt * 8 + tg;
                uint32_t b0 = __float_as_uint(bb[0]);
                uint32_t b1 = __float_as_uint(bb[4]);
                mma8(d[nl][0], d[nl][1], d[nl][2], d[nl][3],
                     uu[0][2 * kt], uu[1][2 * kt],
                     uu[0][2 * kt + 1], uu[1][2 * kt + 1],
                     b0, b1);
            }

        // D -> D_s[t][o' pad36] (region A)
        #pragma unroll
        for (int nl = 0; nl < 4; nl++) {
            int t = mbase + g;
            int oc = nl * 8 + tg * 2;
            sA[t * 36 + oc]           = d[nl][0];
            sA[t * 36 + oc + 1]       = d[nl][1];
            sA[(t + 8) * 36 + oc]     = d[nl][2];
            sA[(t + 8) * 36 + oc + 1] = d[nl][3];
        }
        __syncthreads();

        // remap: out[row0+r][(qn*32+op)*8 + j4*4 + 0..3]
        #pragma unroll
        for (int ii = 0; ii < 4; ii++) {
            int f4 = ii * 256 + tid;           // 1024 float4 per quarter
            int r = f4 >> 6;
            int rem = f4 & 63;
            int op = rem >> 1, j4 = rem & 1;
            if (row0 + r < nrows) {
                float4 v;
                v.x = sA[(r * 8 + j4 * 4 + 0) * 36 + op];
                v.y = sA[(r * 8 + j4 * 4 + 1) * 36 + op];
                v.z = sA[(r * 8 + j4 * 4 + 2) * 36 + op];
                v.w = sA[(r * 8 + j4 * 4 + 3) * 36 + op];
                *(float4*)(out + (size_t)(row0 + r) * 1024 + qn * 256 + op * 8 + j4 * 4) = v;
            }
        }
        __syncthreads();
    }
}

extern "C" void kernel_launch(void* const* d_in, const int* in_sizes, int n_in,
                              void* d_out, int out_size) {
    const float* x   = (const float*)d_in[0];
    const float* wrl = (const float*)d_in[1];
    const float* wrr = (const float*)d_in[2];
    const float* wlf = (const float*)d_in[3];
    float* out = (float*)d_out;

    int nrows = in_sizes[0] / 1024;          // B*S = 8192
    phm_prep<<<16, 256>>>(wrr);
    int grid = (nrows + 15) / 16;            // 16 rows per CTA
    phm_tc<<<grid, 256>>>(x, wrl, wlf, out, nrows);
}